// round 1
// baseline (speedup 1.0000x reference)
#include <cuda_runtime.h>
#include <math.h>

#define S_ 8192
#define D_ 64
#define N_ 2048
#define O_ 8

// LSE scratch (allocation-free rule: __device__ globals)
__device__ float d_lse0[N_];
__device__ float d_lse1[N_];
__device__ float d_lse2[N_];
__device__ float d_lse_out[O_];

// ---------------------------------------------------------------------------
// Kernel A: row-wise logsumexp.
//   blocks [0, N_)           -> rows of w1   (2048 wide)
//   blocks [N_, 2N_)         -> rows of w2   (2048 wide)
//   blocks [2N_, 2N_+O_)     -> rows of w_out (2048 wide)
//   blocks [2N_+O_, +N_/8)   -> 8 rows of w0 each (64 wide, one warp per row)
// Wide rows: 256 threads x 8 elems held in registers -> single pass over HBM.
// ---------------------------------------------------------------------------
__global__ void __launch_bounds__(256) lse_kernel(const float* __restrict__ w0,
                                                  const float* __restrict__ w1,
                                                  const float* __restrict__ w2,
                                                  const float* __restrict__ w_out)
{
    __shared__ float smax[8];
    __shared__ float ssum[8];

    const int b = blockIdx.x;
    const int t = threadIdx.x;
    const int lane = t & 31;
    const int warp = t >> 5;

    if (b < 2 * N_ + O_) {
        // -------- wide rows: 2048 elements --------
        const float* row;
        float* dst;
        if (b < N_)            { row = w1    + (size_t)b * N_;          dst = &d_lse1[b]; }
        else if (b < 2 * N_)   { row = w2    + (size_t)(b - N_) * N_;   dst = &d_lse2[b - N_]; }
        else                   { row = w_out + (size_t)(b - 2*N_) * N_; dst = &d_lse_out[b - 2*N_]; }

        const float4* row4 = (const float4*)row;
        float4 a = row4[t];
        float4 c = row4[t + 256];
        float v[8] = {a.x, a.y, a.z, a.w, c.x, c.y, c.z, c.w};

        float m = v[0];
        #pragma unroll
        for (int i = 1; i < 8; i++) m = fmaxf(m, v[i]);
        #pragma unroll
        for (int off = 16; off; off >>= 1) m = fmaxf(m, __shfl_xor_sync(0xffffffffu, m, off));
        if (lane == 0) smax[warp] = m;
        __syncthreads();
        float bm = smax[0];
        #pragma unroll
        for (int i = 1; i < 8; i++) bm = fmaxf(bm, smax[i]);

        float s = 0.0f;
        #pragma unroll
        for (int i = 0; i < 8; i++) s += expf(v[i] - bm);
        #pragma unroll
        for (int off = 16; off; off >>= 1) s += __shfl_xor_sync(0xffffffffu, s, off);
        if (lane == 0) ssum[warp] = s;
        __syncthreads();
        if (t == 0) {
            float tot = 0.0f;
            #pragma unroll
            for (int i = 0; i < 8; i++) tot += ssum[i];
            *dst = bm + logf(tot);
        }
    } else {
        // -------- w0: 64-wide rows, one warp per row, 8 rows per block --------
        const int r = (b - (2 * N_ + O_)) * 8 + warp;
        const float* row = w0 + (size_t)r * D_;
        float v0 = row[lane];
        float v1 = row[lane + 32];
        float m = fmaxf(v0, v1);
        #pragma unroll
        for (int off = 16; off; off >>= 1) m = fmaxf(m, __shfl_xor_sync(0xffffffffu, m, off));
        float s = expf(v0 - m) + expf(v1 - m);
        #pragma unroll
        for (int off = 16; off; off >>= 1) s += __shfl_xor_sync(0xffffffffu, s, off);
        if (lane == 0) d_lse0[r] = m + logf(s);
    }
}

// ---------------------------------------------------------------------------
// Kernel B: path-walk gather. One thread per (s, o).
// ---------------------------------------------------------------------------
__global__ void __launch_bounds__(256) gather_kernel(const float* __restrict__ x,
                                                     const float* __restrict__ w0,
                                                     const float* __restrict__ w1,
                                                     const float* __restrict__ w2,
                                                     const float* __restrict__ w_out,
                                                     const int* __restrict__ c0,
                                                     const int* __restrict__ c1,
                                                     const int* __restrict__ c2,
                                                     const int* __restrict__ keys_out,
                                                     float* __restrict__ out)
{
    const int tid = blockIdx.x * blockDim.x + threadIdx.x;
    if (tid >= S_ * O_) return;
    const int s = tid >> 3;      // / O_
    const int o = tid & 7;       // % O_

    const int r2 = keys_out[tid];
    float logp = w_out[o * N_ + r2] - d_lse_out[o];

    const int r1 = c2[(size_t)s * N_ + r2];
    logp += w2[(size_t)r2 * N_ + r1] - d_lse2[r2];

    const int r0 = c1[(size_t)s * N_ + r1];
    logp += w1[(size_t)r1 * N_ + r0] - d_lse1[r1];

    const int cin = c0[(size_t)s * N_ + r0];
    logp += w0[r0 * D_ + cin] - d_lse0[r0];

    const float y = sinf(sinf(sinf(x[s * D_ + cin])));

    out[tid] = y;                       // [0, S, O] slice
    out[S_ * O_ + tid] = expf(logp);    // [1, S, O] slice
}

extern "C" void kernel_launch(void* const* d_in, const int* in_sizes, int n_in,
                              void* d_out, int out_size)
{
    const float* x     = (const float*)d_in[0];
    const float* w0    = (const float*)d_in[1];
    const float* w1    = (const float*)d_in[2];
    const float* w2    = (const float*)d_in[3];
    const float* w_out = (const float*)d_in[4];
    const int*   c0    = (const int*)d_in[5];
    const int*   c1    = (const int*)d_in[6];
    const int*   c2    = (const int*)d_in[7];
    const int*   keys  = (const int*)d_in[8];
    float*       out   = (float*)d_out;

    // Kernel A: 2*N_ + O_ wide-row blocks + N_/8 blocks for w0
    const int lse_blocks = 2 * N_ + O_ + N_ / 8;
    lse_kernel<<<lse_blocks, 256>>>(w0, w1, w2, w_out);

    // Kernel B: one thread per (s, o)
    const int total = S_ * O_;
    gather_kernel<<<(total + 255) / 256, 256>>>(x, w0, w1, w2, w_out,
                                                c0, c1, c2, keys, out);
}

// round 2
// speedup vs baseline: 1.0172x; 1.0172x over previous
#include <cuda_runtime.h>
#include <math.h>

#define S_ 8192
#define D_ 64
#define N_ 2048
#define O_ 8
#define GATHER_BLOCKS 256           // 256 blocks x 256 thr = 65536 = S_*O_

// ---- scratch (allocation-free rule: __device__ globals) ----
__device__ float d_lse0[N_];
__device__ float d_lse1[N_];
__device__ float d_lse2[N_];
__device__ float d_lse_out[O_];
__device__ float d_logp_raw[S_ * O_];
__device__ uint2 d_ridx[S_ * O_];   // .x = (r2<<16)|r1, .y = r0

// ---------------------------------------------------------------------------
// Merged kernel: blocks [0, GATHER_BLOCKS) walk the sampled paths (un-normalized
// log-prob) while the remaining blocks compute the row-wise logsumexp tables.
// The two roles are independent; gather blocks go first so they start in wave 1
// and the streaming LSE blocks soak up the DRAM bandwidth the latency-bound
// gather leaves idle.
//   LSE roles (b2 = blockIdx.x - GATHER_BLOCKS):
//     b2 in [0, N_)          -> rows of w1   (2048 wide)
//     b2 in [N_, 2N_)        -> rows of w2   (2048 wide)
//     b2 in [2N_, 2N_+O_)    -> rows of w_out (2048 wide)
//     b2 beyond              -> 8 rows of w0 each (64 wide, one warp per row)
// ---------------------------------------------------------------------------
__global__ void __launch_bounds__(256) lse_gather_kernel(const float* __restrict__ x,
                                                         const float* __restrict__ w0,
                                                         const float* __restrict__ w1,
                                                         const float* __restrict__ w2,
                                                         const float* __restrict__ w_out,
                                                         const int* __restrict__ c0,
                                                         const int* __restrict__ c1,
                                                         const int* __restrict__ c2,
                                                         const int* __restrict__ keys_out,
                                                         float* __restrict__ out)
{
    __shared__ float smax[8];
    __shared__ float ssum[8];

    const int b = blockIdx.x;
    const int t = threadIdx.x;
    const int lane = t & 31;
    const int warp = t >> 5;

    if (b < GATHER_BLOCKS) {
        // ================= path-walk gather (un-normalized) =================
        const int tid = b * 256 + t;
        const int s = tid >> 3;          // / O_
        const int o = tid & 7;           // % O_

        const int r2 = keys_out[tid];
        float logp = w_out[o * N_ + r2];

        const int r1 = c2[(size_t)s * N_ + r2];
        logp += w2[(size_t)r2 * N_ + r1];

        const int r0 = c1[(size_t)s * N_ + r1];
        logp += w1[(size_t)r1 * N_ + r0];

        const int cin = c0[(size_t)s * N_ + r0];
        logp += w0[r0 * D_ + cin];

        const float y = sinf(sinf(sinf(x[s * D_ + cin])));

        out[tid] = y;                                        // [0, S, O] slice
        d_logp_raw[tid] = logp;
        d_ridx[tid] = make_uint2(((unsigned)r2 << 16) | (unsigned)r1,
                                 (unsigned)r0);
        return;
    }

    const int b2 = b - GATHER_BLOCKS;
    if (b2 < 2 * N_ + O_) {
        // ================= wide rows: 2048 elements =================
        const float* row;
        float* dst;
        if (b2 < N_)          { row = w1    + (size_t)b2 * N_;           dst = &d_lse1[b2]; }
        else if (b2 < 2 * N_) { row = w2    + (size_t)(b2 - N_) * N_;    dst = &d_lse2[b2 - N_]; }
        else                  { row = w_out + (size_t)(b2 - 2*N_) * N_;  dst = &d_lse_out[b2 - 2*N_]; }

        const float4* row4 = (const float4*)row;
        float4 a = row4[t];
        float4 c = row4[t + 256];
        float v[8] = {a.x, a.y, a.z, a.w, c.x, c.y, c.z, c.w};

        float m = v[0];
        #pragma unroll
        for (int i = 1; i < 8; i++) m = fmaxf(m, v[i]);
        #pragma unroll
        for (int off = 16; off; off >>= 1) m = fmaxf(m, __shfl_xor_sync(0xffffffffu, m, off));
        if (lane == 0) smax[warp] = m;
        __syncthreads();
        float bm = smax[0];
        #pragma unroll
        for (int i = 1; i < 8; i++) bm = fmaxf(bm, smax[i]);

        float ss = 0.0f;
        #pragma unroll
        for (int i = 0; i < 8; i++) ss += expf(v[i] - bm);
        #pragma unroll
        for (int off = 16; off; off >>= 1) ss += __shfl_xor_sync(0xffffffffu, ss, off);
        if (lane == 0) ssum[warp] = ss;
        __syncthreads();
        if (t == 0) {
            float tot = 0.0f;
            #pragma unroll
            for (int i = 0; i < 8; i++) tot += ssum[i];
            *dst = bm + logf(tot);
        }
    } else {
        // ================= w0: 64-wide rows, one warp per row =================
        const int r = (b2 - (2 * N_ + O_)) * 8 + warp;
        const float* row = w0 + (size_t)r * D_;
        float v0 = row[lane];
        float v1 = row[lane + 32];
        float m = fmaxf(v0, v1);
        #pragma unroll
        for (int off = 16; off; off >>= 1) m = fmaxf(m, __shfl_xor_sync(0xffffffffu, m, off));
        float ss = expf(v0 - m) + expf(v1 - m);
        #pragma unroll
        for (int off = 16; off; off >>= 1) ss += __shfl_xor_sync(0xffffffffu, ss, off);
        if (lane == 0) d_lse0[r] = m + logf(ss);
    }
}

// ---------------------------------------------------------------------------
// Finalize: normalize the stored raw log-probs with the LSE tables (8 KB each,
// L2-hot) and write the probability slice.
// ---------------------------------------------------------------------------
__global__ void __launch_bounds__(256) finalize_kernel(float* __restrict__ out)
{
    const int tid = blockIdx.x * blockDim.x + threadIdx.x;
    if (tid >= S_ * O_) return;
    const int o = tid & 7;

    const uint2 r = d_ridx[tid];
    const int r2 = (int)(r.x >> 16);
    const int r1 = (int)(r.x & 0xFFFFu);
    const int r0 = (int)r.y;

    const float logp = d_logp_raw[tid]
                     - d_lse_out[o] - d_lse2[r2] - d_lse1[r1] - d_lse0[r0];
    out[S_ * O_ + tid] = expf(logp);    // [1, S, O] slice
}

extern "C" void kernel_launch(void* const* d_in, const int* in_sizes, int n_in,
                              void* d_out, int out_size)
{
    const float* x     = (const float*)d_in[0];
    const float* w0    = (const float*)d_in[1];
    const float* w1    = (const float*)d_in[2];
    const float* w2    = (const float*)d_in[3];
    const float* w_out = (const float*)d_in[4];
    const int*   c0    = (const int*)d_in[5];
    const int*   c1    = (const int*)d_in[6];
    const int*   c2    = (const int*)d_in[7];
    const int*   keys  = (const int*)d_in[8];
    float*       out   = (float*)d_out;

    // gather blocks + wide-row LSE blocks + w0 LSE blocks
    const int blocks = GATHER_BLOCKS + (2 * N_ + O_) + N_ / 8;
    lse_gather_kernel<<<blocks, 256>>>(x, w0, w1, w2, w_out,
                                       c0, c1, c2, keys, out);

    const int total = S_ * O_;
    finalize_kernel<<<(total + 255) / 256, 256>>>(out);
}